// round 7
// baseline (speedup 1.0000x reference)
#include <cuda_runtime.h>
#include <cuda_bf16.h>
#include <cuda_fp16.h>

#define NN 100000
#define EE 3200000
#define IND 128
#define HD 64
#define OD 2

#define GEMM1_BLOCKS 296
#define HIST_BLOCKS  1024

// ---- scratch (__device__ globals; zero-initialized at module load) ----
__device__ int    g_cnt[NN];                 // in-degree (excl. self-loop); re-zeroed each call in gemm2
__device__ float  g_dinv[NN];                // rsqrt(deg+1), computed in scan
__device__ int    g_rowstart[NN + 1];        // CSR row offsets (by dst)
__device__ int    g_cursor[NN];              // fill cursors
__device__ int    g_csr[EE];                 // CSR payload: src node ids
__device__ __half g_h1[(size_t)NN * HD];     // fp16: (x @ W1)[r]  UNSCALED   (12.8 MB)
__device__ __half g_a1[(size_t)NN * HD];     // fp16: relu(layer1 out)        (12.8 MB)
__device__ float  g_h2s[(size_t)NN * OD];    // fp32: dinv[r] * (a1 @ W2)[r]

// ---------------- stage A: fused gemm1 (blocks [0,GEMM1_BLOCKS)) + hist (rest) ----------------
// gemm1: g_h1[r] = fp16( x[r] @ W1 )  — no dinv dependency.
// hist:  g_cnt[dst]++ over all edges.

__global__ void __launch_bounds__(256) k_fused_g1_hist(const float* __restrict__ x,
                                                       const float* __restrict__ W1,
                                                       const int* __restrict__ ei,
                                                       int n, int e) {
    __shared__ float Ws[IND * HD];     // 32 KB
    __shared__ float xsT[IND * 32];    // 16 KB, k-major: xsT[k*32 + r]

    if (blockIdx.x >= GEMM1_BLOCKS) {
        // ---- histogram branch ----
        int stride = HIST_BLOCKS * 256;
        int i0 = (blockIdx.x - GEMM1_BLOCKS) * 256 + threadIdx.x;
        for (int i = i0; i < e; i += stride)
            atomicAdd(&g_cnt[ei[(size_t)e + i]], 1);
        return;
    }

    // ---- gemm1 branch ----
    int t = threadIdx.x;
    for (int i = t; i < IND * HD; i += 256) Ws[i] = W1[i];

    int r0 = (t >> 4) * 2;             // 0,2,..,30
    int r1 = r0 + 1;
    int c4 = (t & 15) * 4;             // 0..60
    int ntiles = (n + 31) / 32;

    for (int tile = blockIdx.x; tile < ntiles; tile += GEMM1_BLOCKS) {
        int rowBase = tile * 32;
        __syncthreads();
        for (int i = t; i < 1024; i += 256) {
            int row = i & 31;
            int cc  = (i >> 5) * 4;
            float4 v = make_float4(0.f, 0.f, 0.f, 0.f);
            if (rowBase + row < n)
                v = *(const float4*)&x[(size_t)(rowBase + row) * IND + cc];
            xsT[(cc + 0) * 32 + row] = v.x;
            xsT[(cc + 1) * 32 + row] = v.y;
            xsT[(cc + 2) * 32 + row] = v.z;
            xsT[(cc + 3) * 32 + row] = v.w;
        }
        __syncthreads();

        float a00 = 0.f, a01 = 0.f, a02 = 0.f, a03 = 0.f;
        float a10 = 0.f, a11 = 0.f, a12 = 0.f, a13 = 0.f;
        #pragma unroll 16
        for (int k = 0; k < IND; k++) {
            float4 w = *(const float4*)&Ws[k * HD + c4];
            float x0 = xsT[k * 32 + r0];
            float x1 = xsT[k * 32 + r1];
            a00 += x0 * w.x; a01 += x0 * w.y; a02 += x0 * w.z; a03 += x0 * w.w;
            a10 += x1 * w.x; a11 += x1 * w.y; a12 += x1 * w.z; a13 += x1 * w.w;
        }
        int row0 = rowBase + r0, row1 = rowBase + r1;
        if (row0 < n) {
            size_t o = (size_t)row0 * HD + c4;
            *(__half2*)&g_h1[o]     = __floats2half2_rn(a00, a01);
            *(__half2*)&g_h1[o + 2] = __floats2half2_rn(a02, a03);
        }
        if (row1 < n) {
            size_t o = (size_t)row1 * HD + c4;
            *(__half2*)&g_h1[o]     = __floats2half2_rn(a10, a11);
            *(__half2*)&g_h1[o + 2] = __floats2half2_rn(a12, a13);
        }
    }
}

// ---------------- stage B: single-block scan (rowstart/cursor) + dinv ----------------

__global__ void __launch_bounds__(1024) k_scan(int n, int e) {
    __shared__ int wsum[32];
    int t = threadIdx.x, lane = t & 31, warp = t >> 5;
    int per = (n + 1023) >> 10;
    int beg = t * per;
    int end = min(beg + per, n);

    int s = 0;
    for (int i = beg; i < end; i++) s += g_cnt[i];

    int incl = s;
    #pragma unroll
    for (int o = 1; o < 32; o <<= 1) {
        int v = __shfl_up_sync(0xffffffffu, incl, o);
        if (lane >= o) incl += v;
    }
    if (lane == 31) wsum[warp] = incl;
    __syncthreads();
    if (t < 32) {
        int v = wsum[t], sc = v;
        #pragma unroll
        for (int o = 1; o < 32; o <<= 1) {
            int u = __shfl_up_sync(0xffffffffu, sc, o);
            if (t >= o) sc += u;
        }
        wsum[t] = sc;
    }
    __syncthreads();
    int pref = incl - s + (warp > 0 ? wsum[warp - 1] : 0);  // exclusive prefix of this range

    int run = pref;
    for (int i = beg; i < end; i++) {
        g_rowstart[i] = run;
        g_cursor[i]   = run;
        int c = g_cnt[i];
        g_dinv[i] = rsqrtf((float)c + 1.0f);
        run += c;
    }
    if (t == 0) g_rowstart[n] = e;
}

// ---------------- stage C: CSR fill ----------------

__global__ void k_fill(const int* __restrict__ ei, int e) {
    int stride = gridDim.x * blockDim.x;
    for (int i = blockIdx.x * blockDim.x + threadIdx.x; i < e; i += stride) {
        int src = ei[i];
        int dst = ei[(size_t)e + i];
        int p = atomicAdd(&g_cursor[dst], 1);
        g_csr[p] = src;
    }
}

// ---------------- stage D: gather1 ----------------
// a1[dst] = relu( dinv[dst] * ( sum_src dinv[src]*h1[src] + dinv[dst]*h1[dst] ) + b1 )
// Warp per dst row; lane covers 2 cols via one half2; idx+dinv batched 32-wide.

__global__ void __launch_bounds__(256) k_gather1(const float* __restrict__ b1, int n) {
    int lane = threadIdx.x & 31;
    int row = blockIdx.x * 8 + (threadIdx.x >> 5);
    if (row >= n) return;
    int start = g_rowstart[row];
    int end   = g_rowstart[row + 1];
    int c = lane * 2;
    float drow = g_dinv[row];

    float2 self = __half22float2(*(const __half2*)&g_h1[(size_t)row * HD + c]);
    float2 acc = make_float2(self.x * drow, self.y * drow);

    int j = start;
    while (j + 32 <= end) {
        int   sl = g_csr[j + lane];
        float dl = g_dinv[sl];
        #pragma unroll 8
        for (int k = 0; k < 32; k++) {
            int   s  = __shfl_sync(0xffffffffu, sl, k);
            float ds = __shfl_sync(0xffffffffu, dl, k);
            float2 v = __half22float2(*(const __half2*)&g_h1[(size_t)s * HD + c]);
            acc.x += ds * v.x; acc.y += ds * v.y;
        }
        j += 32;
    }
    if (j < end) {
        int m = end - j;
        int   sl = (lane < m) ? g_csr[j + lane] : 0;
        float dl = (lane < m) ? g_dinv[sl] : 0.f;
        for (int k = 0; k < m; k++) {
            int   s  = __shfl_sync(0xffffffffu, sl, k);
            float ds = __shfl_sync(0xffffffffu, dl, k);
            float2 v = __half22float2(*(const __half2*)&g_h1[(size_t)s * HD + c]);
            acc.x += ds * v.x; acc.y += ds * v.y;
        }
    }
    float r0 = fmaxf(acc.x * drow + b1[c], 0.f);
    float r1 = fmaxf(acc.y * drow + b1[c + 1], 0.f);
    *(__half2*)&g_a1[(size_t)row * HD + c] = __floats2half2_rn(r0, r1);
}

// ---------------- stage E: gemm2 (+ re-zero cnt for next graph replay) ----------------

__global__ void __launch_bounds__(256) k_gemm2(const float* __restrict__ W2, int n) {
    __shared__ float Ws[HD * OD];
    for (int i = threadIdx.x; i < HD * OD; i += blockDim.x) Ws[i] = W2[i];
    __syncthreads();
    int i = blockIdx.x * blockDim.x + threadIdx.x;
    if (i >= n) return;
    g_cnt[i] = 0;                      // cnt dead after scan; ready for next call's hist
    float a0 = 0.f, a1 = 0.f;
    const __half2* h = (const __half2*)&g_a1[(size_t)i * HD];
    #pragma unroll
    for (int k = 0; k < HD / 2; k++) {
        float2 v = __half22float2(h[k]);
        a0 += v.x * Ws[(2 * k) * 2]     + v.y * Ws[(2 * k + 1) * 2];
        a1 += v.x * Ws[(2 * k) * 2 + 1] + v.y * Ws[(2 * k + 1) * 2 + 1];
    }
    float d = g_dinv[i];
    *(float2*)&g_h2s[(size_t)i * OD] = make_float2(a0 * d, a1 * d);
}

// ---------------- stage F: gather2 ----------------

__global__ void __launch_bounds__(256) k_gather2(const float* __restrict__ b2,
                                                 float* __restrict__ out, int n) {
    int lane = threadIdx.x & 31;
    int row = blockIdx.x * 8 + (threadIdx.x >> 5);
    if (row >= n) return;
    int start = g_rowstart[row];
    int end   = g_rowstart[row + 1];

    float2 acc = make_float2(0.f, 0.f);
    for (int j = start + lane; j < end; j += 32) {
        int s = g_csr[j];
        float2 v = *(const float2*)&g_h2s[(size_t)s * OD];
        acc.x += v.x; acc.y += v.y;
    }
    #pragma unroll
    for (int o = 16; o > 0; o >>= 1) {
        acc.x += __shfl_xor_sync(0xffffffffu, acc.x, o);
        acc.y += __shfl_xor_sync(0xffffffffu, acc.y, o);
    }
    if (lane == 0) {
        float2 self = *(const float2*)&g_h2s[(size_t)row * OD];
        float d = g_dinv[row];
        *(float2*)&out[(size_t)row * OD] =
            make_float2((acc.x + self.x) * d + b2[0],
                        (acc.y + self.y) * d + b2[1]);
    }
}

// ---------------- launch ----------------

extern "C" void kernel_launch(void* const* d_in, const int* in_sizes, int n_in,
                              void* d_out, int out_size) {
    const float* x  = (const float*)d_in[0];
    const int*   ei = (const int*)d_in[1];       // int32 (JAX x64 disabled)
    const float* W1 = (const float*)d_in[2];
    const float* b1 = (const float*)d_in[3];
    const float* W2 = (const float*)d_in[4];
    const float* b2 = (const float*)d_in[5];
    float* out = (float*)d_out;

    int n = in_sizes[0] / IND;    // 100000
    int e = in_sizes[1] / 2;      // 3200000
    int nb256 = (n + 255) / 256;

    k_fused_g1_hist<<<GEMM1_BLOCKS + HIST_BLOCKS, 256>>>(x, W1, ei, n, e);  // launch 0
    k_scan   <<<1, 1024>>>(n, e);                                           // launch 1
    k_fill   <<<2048, 256>>>(ei, e);                                        // launch 2
    k_gather1<<<(n + 7) / 8, 256>>>(b1, n);                                 // launch 3  (profiled)
    k_gemm2  <<<nb256, 256>>>(W2, n);                                       // launch 4
    k_gather2<<<(n + 7) / 8, 256>>>(b2, out, n);                            // launch 5
}

// round 9
// speedup vs baseline: 1.9833x; 1.9833x over previous
#include <cuda_runtime.h>
#include <cuda_bf16.h>
#include <cuda_fp16.h>

#define NN 100000
#define EE 3200000
#define IND 128
#define HD 64
#define OD 2

#define GEMM1_BLOCKS 296
#define FILL_BLOCKS  1024

// ---- scratch (__device__ globals; zero-initialized at module load) ----
__device__ int    g_cnt[NN];                 // in-degree (excl. self-loop); re-zeroed in gemm2
__device__ int    g_total;                   // CSR allocator cursor; zeroed in hist
__device__ float  g_dinv[NN];                // rsqrt(deg+1)
__device__ int    g_rowstart[NN];            // CSR region start (by dst)
__device__ int    g_rowend[NN];              // CSR region end
__device__ int    g_cursor[NN];              // fill cursors
__device__ int    g_csr[EE];                 // CSR payload: src node ids
__device__ __half g_h1s[(size_t)NN * HD];    // fp16: dinv[r] * (x @ W1)[r]   (12.8 MB)
__device__ __half g_a1[(size_t)NN * HD];     // fp16: relu(layer1 out)        (12.8 MB)
__device__ float  g_h2s[(size_t)NN * OD];    // fp32: dinv[r] * (a1 @ W2)[r]

// ---------------- launch 0: histogram ----------------

__global__ void k_hist(const int* __restrict__ ei, int e) {
    if (blockIdx.x == 0 && threadIdx.x == 0) g_total = 0;   // reset allocator (safe: used only after this kernel)
    int stride = gridDim.x * blockDim.x;
    for (int i = blockIdx.x * blockDim.x + threadIdx.x; i < e; i += stride)
        atomicAdd(&g_cnt[ei[(size_t)e + i]], 1);
}

// ---------------- launch 1: CSR region allocation (block-aggregated atomic) ----------------
// Regions need only be disjoint+contiguous, not an ordered prefix -> no global scan.

__global__ void __launch_bounds__(256) k_offsets(int n) {
    __shared__ int wtot[8];
    __shared__ int sbase;
    int t = threadIdx.x, lane = t & 31, warp = t >> 5;
    int i = blockIdx.x * 256 + t;
    int c = (i < n) ? g_cnt[i] : 0;

    int incl = c;
    #pragma unroll
    for (int o = 1; o < 32; o <<= 1) {
        int v = __shfl_up_sync(0xffffffffu, incl, o);
        if (lane >= o) incl += v;
    }
    if (lane == 31) wtot[warp] = incl;
    __syncthreads();
    if (t < 8) {
        int v = wtot[t], s = v;
        #pragma unroll
        for (int o = 1; o < 8; o <<= 1) {
            int u = __shfl_up_sync(0xffu, s, o);
            if (t >= o) s += u;
        }
        wtot[t] = s;
    }
    __syncthreads();
    if (t == 0) sbase = atomicAdd(&g_total, wtot[7]);
    __syncthreads();

    if (i < n) {
        int off = sbase + incl - c + (warp > 0 ? wtot[warp - 1] : 0);
        g_rowstart[i] = off;
        g_cursor[i]   = off;
        g_rowend[i]   = off + c;
        g_dinv[i]     = rsqrtf((float)c + 1.0f);
    }
}

// ---------------- launch 2: fused gemm1 (blocks [0,GEMM1_BLOCKS)) + CSR fill (rest) ----------------
// gemm1: g_h1s[r] = fp16( dinv[r] * (x[r] @ W1) )   (prescaled by src-side dinv)
// fill:  g_csr[cursor[dst]++] = src

__global__ void __launch_bounds__(256) k_fused_g1_fill(const float* __restrict__ x,
                                                       const float* __restrict__ W1,
                                                       const int* __restrict__ ei,
                                                       int n, int e) {
    __shared__ float Ws[IND * HD];     // 32 KB
    __shared__ float xsT[IND * 32];    // 16 KB, k-major: xsT[k*32 + r]

    if (blockIdx.x >= GEMM1_BLOCKS) {
        // ---- fill branch ----
        int stride = FILL_BLOCKS * 256;
        int i0 = (blockIdx.x - GEMM1_BLOCKS) * 256 + threadIdx.x;
        for (int i = i0; i < e; i += stride) {
            int src = ei[i];
            int dst = ei[(size_t)e + i];
            int p = atomicAdd(&g_cursor[dst], 1);
            g_csr[p] = src;
        }
        return;
    }

    // ---- gemm1 branch ----
    int t = threadIdx.x;
    for (int i = t; i < IND * HD; i += 256) Ws[i] = W1[i];

    int r0 = (t >> 4) * 2;             // 0,2,..,30
    int r1 = r0 + 1;
    int c4 = (t & 15) * 4;             // 0..60
    int ntiles = (n + 31) / 32;

    for (int tile = blockIdx.x; tile < ntiles; tile += GEMM1_BLOCKS) {
        int rowBase = tile * 32;
        __syncthreads();
        for (int i = t; i < 1024; i += 256) {
            int row = i & 31;
            int cc  = (i >> 5) * 4;
            float4 v = make_float4(0.f, 0.f, 0.f, 0.f);
            if (rowBase + row < n)
                v = *(const float4*)&x[(size_t)(rowBase + row) * IND + cc];
            xsT[(cc + 0) * 32 + row] = v.x;
            xsT[(cc + 1) * 32 + row] = v.y;
            xsT[(cc + 2) * 32 + row] = v.z;
            xsT[(cc + 3) * 32 + row] = v.w;
        }
        __syncthreads();

        float a00 = 0.f, a01 = 0.f, a02 = 0.f, a03 = 0.f;
        float a10 = 0.f, a11 = 0.f, a12 = 0.f, a13 = 0.f;
        #pragma unroll 16
        for (int k = 0; k < IND; k++) {
            float4 w = *(const float4*)&Ws[k * HD + c4];
            float x0 = xsT[k * 32 + r0];
            float x1 = xsT[k * 32 + r1];
            a00 += x0 * w.x; a01 += x0 * w.y; a02 += x0 * w.z; a03 += x0 * w.w;
            a10 += x1 * w.x; a11 += x1 * w.y; a12 += x1 * w.z; a13 += x1 * w.w;
        }
        int row0 = rowBase + r0, row1 = rowBase + r1;
        if (row0 < n) {
            float d = g_dinv[row0];
            size_t o = (size_t)row0 * HD + c4;
            *(__half2*)&g_h1s[o]     = __floats2half2_rn(a00 * d, a01 * d);
            *(__half2*)&g_h1s[o + 2] = __floats2half2_rn(a02 * d, a03 * d);
        }
        if (row1 < n) {
            float d = g_dinv[row1];
            size_t o = (size_t)row1 * HD + c4;
            *(__half2*)&g_h1s[o]     = __floats2half2_rn(a10 * d, a11 * d);
            *(__half2*)&g_h1s[o + 2] = __floats2half2_rn(a12 * d, a13 * d);
        }
    }
}

// ---------------- launch 3 (profiled): gather1 ----------------
// a1[dst] = relu( dinv[dst] * ( sum_src h1s[src] + h1s[dst] ) + b1 )
// Warp per dst row; lane covers 2 cols via one half2; 1 shfl + 1 LDG per edge.

__global__ void __launch_bounds__(256) k_gather1(const float* __restrict__ b1, int n) {
    int lane = threadIdx.x & 31;
    int row = blockIdx.x * 8 + (threadIdx.x >> 5);
    if (row >= n) return;
    int start = g_rowstart[row];
    int end   = g_rowend[row];
    int c = lane * 2;

    float2 acc = __half22float2(*(const __half2*)&g_h1s[(size_t)row * HD + c]);  // self (prescaled)
    int j = start;
    while (j + 32 <= end) {
        int idx = g_csr[j + lane];
        #pragma unroll 8
        for (int k = 0; k < 32; k++) {
            int s = __shfl_sync(0xffffffffu, idx, k);
            float2 v = __half22float2(*(const __half2*)&g_h1s[(size_t)s * HD + c]);
            acc.x += v.x; acc.y += v.y;
        }
        j += 32;
    }
    if (j < end) {
        int m = end - j;
        int idx = (lane < m) ? g_csr[j + lane] : 0;
        for (int k = 0; k < m; k++) {
            int s = __shfl_sync(0xffffffffu, idx, k);
            float2 v = __half22float2(*(const __half2*)&g_h1s[(size_t)s * HD + c]);
            acc.x += v.x; acc.y += v.y;
        }
    }
    float drow = g_dinv[row];
    float r0 = fmaxf(acc.x * drow + b1[c], 0.f);
    float r1 = fmaxf(acc.y * drow + b1[c + 1], 0.f);
    *(__half2*)&g_a1[(size_t)row * HD + c] = __floats2half2_rn(r0, r1);
}

// ---------------- launch 4: gemm2 (+ re-zero cnt for next graph replay) ----------------

__global__ void __launch_bounds__(256) k_gemm2(const float* __restrict__ W2, int n) {
    __shared__ float Ws[HD * OD];
    for (int i = threadIdx.x; i < HD * OD; i += blockDim.x) Ws[i] = W2[i];
    __syncthreads();
    int i = blockIdx.x * blockDim.x + threadIdx.x;
    if (i >= n) return;
    g_cnt[i] = 0;                      // cnt dead after offsets; ready for next call's hist
    float a0 = 0.f, a1 = 0.f;
    const __half2* h = (const __half2*)&g_a1[(size_t)i * HD];
    #pragma unroll
    for (int k = 0; k < HD / 2; k++) {
        float2 v = __half22float2(h[k]);
        a0 += v.x * Ws[(2 * k) * 2]     + v.y * Ws[(2 * k + 1) * 2];
        a1 += v.x * Ws[(2 * k) * 2 + 1] + v.y * Ws[(2 * k + 1) * 2 + 1];
    }
    float d = g_dinv[i];
    *(float2*)&g_h2s[(size_t)i * OD] = make_float2(a0 * d, a1 * d);
}

// ---------------- launch 5: gather2 ----------------

__global__ void __launch_bounds__(256) k_gather2(const float* __restrict__ b2,
                                                 float* __restrict__ out, int n) {
    int lane = threadIdx.x & 31;
    int row = blockIdx.x * 8 + (threadIdx.x >> 5);
    if (row >= n) return;
    int start = g_rowstart[row];
    int end   = g_rowend[row];

    float2 acc = make_float2(0.f, 0.f);
    for (int j = start + lane; j < end; j += 32) {
        int s = g_csr[j];
        float2 v = *(const float2*)&g_h2s[(size_t)s * OD];
        acc.x += v.x; acc.y += v.y;
    }
    #pragma unroll
    for (int o = 16; o > 0; o >>= 1) {
        acc.x += __shfl_xor_sync(0xffffffffu, acc.x, o);
        acc.y += __shfl_xor_sync(0xffffffffu, acc.y, o);
    }
    if (lane == 0) {
        float2 self = *(const float2*)&g_h2s[(size_t)row * OD];
        float d = g_dinv[row];
        *(float2*)&out[(size_t)row * OD] =
            make_float2((acc.x + self.x) * d + b2[0],
                        (acc.y + self.y) * d + b2[1]);
    }
}

// ---------------- launch ----------------

extern "C" void kernel_launch(void* const* d_in, const int* in_sizes, int n_in,
                              void* d_out, int out_size) {
    const float* x  = (const float*)d_in[0];
    const int*   ei = (const int*)d_in[1];       // int32 (JAX x64 disabled)
    const float* W1 = (const float*)d_in[2];
    const float* b1 = (const float*)d_in[3];
    const float* W2 = (const float*)d_in[4];
    const float* b2 = (const float*)d_in[5];
    float* out = (float*)d_out;

    int n = in_sizes[0] / IND;    // 100000
    int e = in_sizes[1] / 2;      // 3200000
    int nb256 = (n + 255) / 256;

    k_hist         <<<2048, 256>>>(ei, e);                              // 0
    k_offsets      <<<nb256, 256>>>(n);                                 // 1
    k_fused_g1_fill<<<GEMM1_BLOCKS + FILL_BLOCKS, 256>>>(x, W1, ei, n, e); // 2
    k_gather1      <<<(n + 7) / 8, 256>>>(b1, n);                       // 3  (profiled)
    k_gemm2        <<<nb256, 256>>>(W2, n);                             // 4
    k_gather2      <<<(n + 7) / 8, 256>>>(b2, out, n);                  // 5
}

// round 10
// speedup vs baseline: 2.5592x; 1.2904x over previous
#include <cuda_runtime.h>
#include <cuda_bf16.h>
#include <cuda_fp16.h>

#define NN 100000
#define EE 3200000
#define IND 128
#define HD 64
#define OD 2

#define GEMM1_BLOCKS 391
#define FILL_BLOCKS  1024
#define TILE_R 128

// ---- scratch (__device__ globals; zero-initialized at module load) ----
__device__ int    g_cnt[NN];                 // in-degree (excl. self-loop); re-zeroed in gemm2
__device__ int    g_total;                   // CSR allocator cursor; reset in hist
__device__ float  g_dinv[NN];                // rsqrt(deg+1)
__device__ int    g_rowstart[NN];            // CSR region start (by dst)
__device__ int    g_rowend[NN];              // CSR region end
__device__ int    g_cursor[NN];              // fill cursors
__device__ int    g_csr[EE];                 // CSR payload: src node ids
__device__ __half g_h1s[(size_t)NN * HD];    // fp16: dinv[r] * (x @ W1)[r]
__device__ __half g_a1[(size_t)NN * HD];     // fp16: relu(layer1 out)
__device__ float  g_h2s[(size_t)NN * OD];    // fp32: dinv[r] * (a1 @ W2)[r]

// ---------------- launch 0: histogram ----------------

__global__ void k_hist(const int* __restrict__ ei, int e) {
    if (blockIdx.x == 0 && threadIdx.x == 0) g_total = 0;
    int stride = gridDim.x * blockDim.x;
    for (int i = blockIdx.x * blockDim.x + threadIdx.x; i < e; i += stride)
        atomicAdd(&g_cnt[ei[(size_t)e + i]], 1);
}

// ---------------- launch 1: CSR region allocation (block-aggregated atomic) ----------------

__global__ void __launch_bounds__(256) k_offsets(int n) {
    __shared__ int wtot[8];
    __shared__ int sbase;
    int t = threadIdx.x, lane = t & 31, warp = t >> 5;
    int i = blockIdx.x * 256 + t;
    int c = (i < n) ? g_cnt[i] : 0;

    int incl = c;
    #pragma unroll
    for (int o = 1; o < 32; o <<= 1) {
        int v = __shfl_up_sync(0xffffffffu, incl, o);
        if (lane >= o) incl += v;
    }
    if (lane == 31) wtot[warp] = incl;
    __syncthreads();
    if (t < 8) {
        int v = wtot[t], s = v;
        #pragma unroll
        for (int o = 1; o < 8; o <<= 1) {
            int u = __shfl_up_sync(0xffu, s, o);
            if (t >= o) s += u;
        }
        wtot[t] = s;
    }
    __syncthreads();
    if (t == 0) sbase = atomicAdd(&g_total, wtot[7]);
    __syncthreads();

    if (i < n) {
        int off = sbase + incl - c + (warp > 0 ? wtot[warp - 1] : 0);
        g_rowstart[i] = off;
        g_cursor[i]   = off;
        g_rowend[i]   = off + c;
        g_dinv[i]     = rsqrtf((float)c + 1.0f);
    }
}

// ---------------- launch 2: fused gemm1 + CSR fill ----------------
// gemm1 (blocks [0,GEMM1_BLOCKS)): g_h1s[r] = fp16( dinv[r] * (x[r] @ W1) )
//   128-row tiles, thread = 8 rows x 4 cols (32 acc). 96KB dynamic smem.
// fill (remaining blocks): g_csr[cursor[dst]++] = src

extern __shared__ float s_dyn[];

__global__ void __launch_bounds__(256) k_fused_g1_fill(const float* __restrict__ x,
                                                       const float* __restrict__ W1,
                                                       const int* __restrict__ ei,
                                                       int n, int e) {
    if (blockIdx.x >= GEMM1_BLOCKS) {
        // ---- fill branch ----
        int stride = FILL_BLOCKS * 256;
        int i0 = (blockIdx.x - GEMM1_BLOCKS) * 256 + threadIdx.x;
        for (int i = i0; i < e; i += stride) {
            int src = ei[i];
            int dst = ei[(size_t)e + i];
            int p = atomicAdd(&g_cursor[dst], 1);
            g_csr[p] = src;
        }
        return;
    }

    // ---- gemm1 branch ----
    float* Ws   = s_dyn;            // [128*64]  32 KB, k-major (same as W1 layout)
    float* x_rm = s_dyn + IND * HD; // [128*128] 64 KB, row-major [r][k]

    int t = threadIdx.x;
    for (int i = t; i < IND * HD; i += 256) Ws[i] = W1[i];

    int rg = t >> 4;            // 0..15 -> rows rg*8 .. rg*8+7
    int cg = t & 15;            // cols cg*4 .. cg*4+3
    int ntiles = (n + TILE_R - 1) / TILE_R;

    for (int tile = blockIdx.x; tile < ntiles; tile += GEMM1_BLOCKS) {
        int rowBase = tile * TILE_R;
        __syncthreads();
        // load 128x128 x-tile, row-major, coalesced (warp = one row, lanes = float4 cols)
        for (int i = t; i < TILE_R * 32; i += 256) {
            int r  = i >> 5;
            int c4 = (i & 31) * 4;
            float4 v = make_float4(0.f, 0.f, 0.f, 0.f);
            if (rowBase + r < n)
                v = *(const float4*)&x[(size_t)(rowBase + r) * IND + c4];
            *(float4*)&x_rm[r * IND + c4] = v;
        }
        __syncthreads();

        float4 a0 = {0,0,0,0}, a1 = {0,0,0,0}, a2 = {0,0,0,0}, a3 = {0,0,0,0};
        float4 a4 = {0,0,0,0}, a5 = {0,0,0,0}, a6 = {0,0,0,0}, a7 = {0,0,0,0};
        const float* xr = &x_rm[(rg * 8) * IND];
        #pragma unroll 8
        for (int k = 0; k < IND; k++) {
            float4 w = *(const float4*)&Ws[k * HD + cg * 4];
            float x0 = xr[0 * IND + k];
            float x1 = xr[1 * IND + k];
            float x2 = xr[2 * IND + k];
            float x3 = xr[3 * IND + k];
            float x4 = xr[4 * IND + k];
            float x5 = xr[5 * IND + k];
            float x6 = xr[6 * IND + k];
            float x7 = xr[7 * IND + k];
            a0.x += x0*w.x; a0.y += x0*w.y; a0.z += x0*w.z; a0.w += x0*w.w;
            a1.x += x1*w.x; a1.y += x1*w.y; a1.z += x1*w.z; a1.w += x1*w.w;
            a2.x += x2*w.x; a2.y += x2*w.y; a2.z += x2*w.z; a2.w += x2*w.w;
            a3.x += x3*w.x; a3.y += x3*w.y; a3.z += x3*w.z; a3.w += x3*w.w;
            a4.x += x4*w.x; a4.y += x4*w.y; a4.z += x4*w.z; a4.w += x4*w.w;
            a5.x += x5*w.x; a5.y += x5*w.y; a5.z += x5*w.z; a5.w += x5*w.w;
            a6.x += x6*w.x; a6.y += x6*w.y; a6.z += x6*w.z; a6.w += x6*w.w;
            a7.x += x7*w.x; a7.y += x7*w.y; a7.z += x7*w.z; a7.w += x7*w.w;
        }

        float4 acc[8] = {a0, a1, a2, a3, a4, a5, a6, a7};
        #pragma unroll
        for (int i = 0; i < 8; i++) {
            int row = rowBase + rg * 8 + i;
            if (row < n) {
                float d = g_dinv[row];
                size_t o = (size_t)row * HD + cg * 4;
                *(__half2*)&g_h1s[o]     = __floats2half2_rn(acc[i].x * d, acc[i].y * d);
                *(__half2*)&g_h1s[o + 2] = __floats2half2_rn(acc[i].z * d, acc[i].w * d);
            }
        }
    }
}

// ---------------- launch 3 (profiled): gather1 ----------------
// a1[dst] = relu( dinv[dst] * ( sum_src h1s[src] + h1s[dst] ) + b1 )
// Warp per dst row; lane = 2 cols (half2). Edge PAIRS summed in fp16 (HADD2),
// converted once per pair -> CVT/edge halved. fp32 accumulate.

__global__ void __launch_bounds__(256) k_gather1(const float* __restrict__ b1, int n) {
    int lane = threadIdx.x & 31;
    int row = blockIdx.x * 8 + (threadIdx.x >> 5);
    if (row >= n) return;
    int start = g_rowstart[row];
    int end   = g_rowend[row];
    const __half2* hb = (const __half2*)g_h1s + lane;   // lane's column pair

    float2 acc = __half22float2(hb[(size_t)row * 32]);  // self (prescaled)
    int j = start;
    while (j + 32 <= end) {
        int idx = g_csr[j + lane];
        #pragma unroll
        for (int k = 0; k < 32; k += 2) {
            int s0 = __shfl_sync(0xffffffffu, idx, k);
            int s1 = __shfl_sync(0xffffffffu, idx, k + 1);
            __half2 v = __hadd2(hb[(size_t)s0 * 32], hb[(size_t)s1 * 32]);
            float2 f = __half22float2(v);
            acc.x += f.x; acc.y += f.y;
        }
        j += 32;
    }
    int m = end - j;
    if (m > 0) {
        int idx = (lane < m) ? g_csr[j + lane] : 0;
        int k = 0;
        for (; k + 2 <= m; k += 2) {
            int s0 = __shfl_sync(0xffffffffu, idx, k);
            int s1 = __shfl_sync(0xffffffffu, idx, k + 1);
            __half2 v = __hadd2(hb[(size_t)s0 * 32], hb[(size_t)s1 * 32]);
            float2 f = __half22float2(v);
            acc.x += f.x; acc.y += f.y;
        }
        if (k < m) {
            int s0 = __shfl_sync(0xffffffffu, idx, k);
            float2 f = __half22float2(hb[(size_t)s0 * 32]);
            acc.x += f.x; acc.y += f.y;
        }
    }
    float drow = g_dinv[row];
    int c = lane * 2;
    float r0 = fmaxf(acc.x * drow + b1[c], 0.f);
    float r1 = fmaxf(acc.y * drow + b1[c + 1], 0.f);
    *(__half2*)&g_a1[(size_t)row * HD + c] = __floats2half2_rn(r0, r1);
}

// ---------------- launch 4: gemm2 (+ re-zero cnt for next graph replay) ----------------

__global__ void __launch_bounds__(256) k_gemm2(const float* __restrict__ W2, int n) {
    __shared__ float Ws[HD * OD];
    for (int i = threadIdx.x; i < HD * OD; i += blockDim.x) Ws[i] = W2[i];
    __syncthreads();
    int i = blockIdx.x * blockDim.x + threadIdx.x;
    if (i >= n) return;
    g_cnt[i] = 0;
    float a0 = 0.f, a1 = 0.f;
    const __half2* h = (const __half2*)&g_a1[(size_t)i * HD];
    #pragma unroll
    for (int k = 0; k < HD / 2; k++) {
        float2 v = __half22float2(h[k]);
        a0 += v.x * Ws[(2 * k) * 2]     + v.y * Ws[(2 * k + 1) * 2];
        a1 += v.x * Ws[(2 * k) * 2 + 1] + v.y * Ws[(2 * k + 1) * 2 + 1];
    }
    float d = g_dinv[i];
    *(float2*)&g_h2s[(size_t)i * OD] = make_float2(a0 * d, a1 * d);
}

// ---------------- launch 5: gather2 ----------------

__global__ void __launch_bounds__(256) k_gather2(const float* __restrict__ b2,
                                                 float* __restrict__ out, int n) {
    int lane = threadIdx.x & 31;
    int row = blockIdx.x * 8 + (threadIdx.x >> 5);
    if (row >= n) return;
    int start = g_rowstart[row];
    int end   = g_rowend[row];

    float2 acc = make_float2(0.f, 0.f);
    for (int j = start + lane; j < end; j += 32) {
        int s = g_csr[j];
        float2 v = *(const float2*)&g_h2s[(size_t)s * OD];
        acc.x += v.x; acc.y += v.y;
    }
    #pragma unroll
    for (int o = 16; o > 0; o >>= 1) {
        acc.x += __shfl_xor_sync(0xffffffffu, acc.x, o);
        acc.y += __shfl_xor_sync(0xffffffffu, acc.y, o);
    }
    if (lane == 0) {
        float2 self = *(const float2*)&g_h2s[(size_t)row * OD];
        float d = g_dinv[row];
        *(float2*)&out[(size_t)row * OD] =
            make_float2((acc.x + self.x) * d + b2[0],
                        (acc.y + self.y) * d + b2[1]);
    }
}

// ---------------- launch ----------------

extern "C" void kernel_launch(void* const* d_in, const int* in_sizes, int n_in,
                              void* d_out, int out_size) {
    const float* x  = (const float*)d_in[0];
    const int*   ei = (const int*)d_in[1];       // int32 (JAX x64 disabled)
    const float* W1 = (const float*)d_in[2];
    const float* b1 = (const float*)d_in[3];
    const float* W2 = (const float*)d_in[4];
    const float* b2 = (const float*)d_in[5];
    float* out = (float*)d_out;

    int n = in_sizes[0] / IND;    // 100000
    int e = in_sizes[1] / 2;      // 3200000
    int nb256 = (n + 255) / 256;

    const int SMEM = (IND * HD + TILE_R * IND) * sizeof(float);   // 96 KB
    cudaFuncSetAttribute(k_fused_g1_fill,
                         cudaFuncAttributeMaxDynamicSharedMemorySize, SMEM);

    k_hist         <<<2048, 256>>>(ei, e);                                   // 0
    k_offsets      <<<nb256, 256>>>(n);                                      // 1
    k_fused_g1_fill<<<GEMM1_BLOCKS + FILL_BLOCKS, 256, SMEM>>>(x, W1, ei, n, e); // 2
    k_gather1      <<<(n + 7) / 8, 256>>>(b1, n);                            // 3 (profiled)
    k_gemm2        <<<nb256, 256>>>(W2, n);                                  // 4
    k_gather2      <<<(n + 7) / 8, 256>>>(b2, out, n);                       // 5
}

// round 11
// speedup vs baseline: 2.6876x; 1.0502x over previous
#include <cuda_runtime.h>
#include <cuda_bf16.h>
#include <cuda_fp16.h>

#define NN 100000
#define EE 3200000
#define IND 128
#define HD 64
#define OD 2

#define GEMM1_BLOCKS 391
#define TILE_R 128

// ---- scratch (__device__ globals; zero-initialized at module load) ----
__device__ int    g_cnt[NN];                 // in-degree (excl. self-loop); re-zeroed in gather2
__device__ int    g_total;                   // CSR allocator cursor; reset in hist
__device__ float  g_dinv[NN];                // rsqrt(deg+1)
__device__ int    g_rowstart[NN];            // CSR region start (by dst)
__device__ int    g_rowend[NN];              // CSR region end
__device__ int    g_cursor[NN];              // fill cursors
__device__ int    g_csr[EE];                 // CSR payload: src node ids
__device__ __half g_h1s[(size_t)NN * HD];    // fp16: (x @ W1)[r], then scaled by dinv[r]
__device__ float  g_h2s[(size_t)NN * OD];    // fp32: dinv[r] * (relu(l1) @ W2)[r]

// ---------------- histogram (stream 0) ----------------

__global__ void k_hist(const int* __restrict__ ei, int e) {
    if (blockIdx.x == 0 && threadIdx.x == 0) g_total = 0;
    int stride = gridDim.x * blockDim.x;
    for (int i = blockIdx.x * blockDim.x + threadIdx.x; i < e; i += stride)
        atomicAdd(&g_cnt[ei[(size_t)e + i]], 1);
}

// ---------------- CSR region allocation (block-aggregated atomic) ----------------

__global__ void __launch_bounds__(256) k_offsets(int n) {
    __shared__ int wtot[8];
    __shared__ int sbase;
    int t = threadIdx.x, lane = t & 31, warp = t >> 5;
    int i = blockIdx.x * 256 + t;
    int c = (i < n) ? g_cnt[i] : 0;

    int incl = c;
    #pragma unroll
    for (int o = 1; o < 32; o <<= 1) {
        int v = __shfl_up_sync(0xffffffffu, incl, o);
        if (lane >= o) incl += v;
    }
    if (lane == 31) wtot[warp] = incl;
    __syncthreads();
    if (t < 8) {
        int v = wtot[t], s = v;
        #pragma unroll
        for (int o = 1; o < 8; o <<= 1) {
            int u = __shfl_up_sync(0xffu, s, o);
            if (t >= o) s += u;
        }
        wtot[t] = s;
    }
    __syncthreads();
    if (t == 0) sbase = atomicAdd(&g_total, wtot[7]);
    __syncthreads();

    if (i < n) {
        int off = sbase + incl - c + (warp > 0 ? wtot[warp - 1] : 0);
        g_rowstart[i] = off;
        g_cursor[i]   = off;
        g_rowend[i]   = off + c;
        g_dinv[i]     = rsqrtf((float)c + 1.0f);
    }
}

// ---------------- CSR fill (stream 0; no smem -> full occupancy) ----------------

__global__ void k_fill(const int* __restrict__ ei, int e) {
    int stride = gridDim.x * blockDim.x;
    for (int i = blockIdx.x * blockDim.x + threadIdx.x; i < e; i += stride) {
        int src = ei[i];
        int dst = ei[(size_t)e + i];
        int p = atomicAdd(&g_cursor[dst], 1);
        g_csr[p] = src;
    }
}

// ---------------- gemm1 (stream 2, concurrent): g_h1s[r] = fp16( x[r] @ W1 ) unscaled ----------------
// 128-row tiles, thread = 8 rows x 4 cols (32 acc). 96KB dynamic smem.

extern __shared__ float s_dyn[];

__global__ void __launch_bounds__(256) k_gemm1(const float* __restrict__ x,
                                               const float* __restrict__ W1, int n) {
    float* Ws   = s_dyn;            // [128*64]  32 KB
    float* x_rm = s_dyn + IND * HD; // [128*128] 64 KB, row-major [r][k]

    int t = threadIdx.x;
    for (int i = t; i < IND * HD; i += 256) Ws[i] = W1[i];

    int rg = t >> 4;            // 0..15 -> rows rg*8 .. rg*8+7
    int cg = t & 15;            // cols cg*4 .. cg*4+3
    int ntiles = (n + TILE_R - 1) / TILE_R;

    for (int tile = blockIdx.x; tile < ntiles; tile += GEMM1_BLOCKS) {
        int rowBase = tile * TILE_R;
        __syncthreads();
        for (int i = t; i < TILE_R * 32; i += 256) {
            int r  = i >> 5;
            int c4 = (i & 31) * 4;
            float4 v = make_float4(0.f, 0.f, 0.f, 0.f);
            if (rowBase + r < n)
                v = *(const float4*)&x[(size_t)(rowBase + r) * IND + c4];
            *(float4*)&x_rm[r * IND + c4] = v;
        }
        __syncthreads();

        float4 a0 = {0,0,0,0}, a1 = {0,0,0,0}, a2 = {0,0,0,0}, a3 = {0,0,0,0};
        float4 a4 = {0,0,0,0}, a5 = {0,0,0,0}, a6 = {0,0,0,0}, a7 = {0,0,0,0};
        const float* xr = &x_rm[(rg * 8) * IND];
        #pragma unroll 8
        for (int k = 0; k < IND; k++) {
            float4 w = *(const float4*)&Ws[k * HD + cg * 4];
            float x0 = xr[0 * IND + k];
            float x1 = xr[1 * IND + k];
            float x2 = xr[2 * IND + k];
            float x3 = xr[3 * IND + k];
            float x4 = xr[4 * IND + k];
            float x5 = xr[5 * IND + k];
            float x6 = xr[6 * IND + k];
            float x7 = xr[7 * IND + k];
            a0.x += x0*w.x; a0.y += x0*w.y; a0.z += x0*w.z; a0.w += x0*w.w;
            a1.x += x1*w.x; a1.y += x1*w.y; a1.z += x1*w.z; a1.w += x1*w.w;
            a2.x += x2*w.x; a2.y += x2*w.y; a2.z += x2*w.z; a2.w += x2*w.w;
            a3.x += x3*w.x; a3.y += x3*w.y; a3.z += x3*w.z; a3.w += x3*w.w;
            a4.x += x4*w.x; a4.y += x4*w.y; a4.z += x4*w.z; a4.w += x4*w.w;
            a5.x += x5*w.x; a5.y += x5*w.y; a5.z += x5*w.z; a5.w += x5*w.w;
            a6.x += x6*w.x; a6.y += x6*w.y; a6.z += x6*w.z; a6.w += x6*w.w;
            a7.x += x7*w.x; a7.y += x7*w.y; a7.z += x7*w.z; a7.w += x7*w.w;
        }

        float4 acc[8] = {a0, a1, a2, a3, a4, a5, a6, a7};
        #pragma unroll
        for (int i = 0; i < 8; i++) {
            int row = rowBase + rg * 8 + i;
            if (row < n) {
                size_t o = (size_t)row * HD + cg * 4;
                *(__half2*)&g_h1s[o]     = __floats2half2_rn(acc[i].x, acc[i].y);
                *(__half2*)&g_h1s[o + 2] = __floats2half2_rn(acc[i].z, acc[i].w);
            }
        }
    }
}

// ---------------- scale: h1s[r] *= dinv[r]   (after join; L2-resident, ~3us) ----------------

__global__ void k_scale(int n) {
    int i = blockIdx.x * blockDim.x + threadIdx.x;   // half2 index
    if (i >= n * (HD / 2)) return;
    int row = i >> 5;                                 // 32 half2 per row
    __half2 d = __float2half2_rn(g_dinv[row]);
    __half2* p = (__half2*)g_h1s + i;
    *p = __hmul2(*p, d);
}

// ---------------- gather1 + gemm2 fused ----------------
// a1(row,c) = relu(dinv[row]*(sum h1s[src] + h1s[row]) + b1[c])  (in registers)
// h2s[row]  = dinv[row] * (a1(row,:) @ W2)   via 2 warp butterflies

__global__ void __launch_bounds__(256) k_gather1f(const float* __restrict__ b1,
                                                  const float* __restrict__ W2, int n) {
    int lane = threadIdx.x & 31;
    int row = blockIdx.x * 8 + (threadIdx.x >> 5);
    if (row >= n) return;
    int start = g_rowstart[row];
    int end   = g_rowend[row];
    const __half2* hb = (const __half2*)g_h1s + lane;   // lane's column pair

    float2 acc = __half22float2(hb[(size_t)row * 32]);  // self (prescaled)
    int j = start;
    while (j + 32 <= end) {
        int idx = g_csr[j + lane];
        #pragma unroll
        for (int k = 0; k < 32; k += 2) {
            int s0 = __shfl_sync(0xffffffffu, idx, k);
            int s1 = __shfl_sync(0xffffffffu, idx, k + 1);
            __half2 v = __hadd2(hb[(size_t)s0 * 32], hb[(size_t)s1 * 32]);
            float2 f = __half22float2(v);
            acc.x += f.x; acc.y += f.y;
        }
        j += 32;
    }
    int m = end - j;
    if (m > 0) {
        int idx = (lane < m) ? g_csr[j + lane] : 0;
        int k = 0;
        for (; k + 2 <= m; k += 2) {
            int s0 = __shfl_sync(0xffffffffu, idx, k);
            int s1 = __shfl_sync(0xffffffffu, idx, k + 1);
            __half2 v = __hadd2(hb[(size_t)s0 * 32], hb[(size_t)s1 * 32]);
            float2 f = __half22float2(v);
            acc.x += f.x; acc.y += f.y;
        }
        if (k < m) {
            int s0 = __shfl_sync(0xffffffffu, idx, k);
            float2 f = __half22float2(hb[(size_t)s0 * 32]);
            acc.x += f.x; acc.y += f.y;
        }
    }
    float drow = g_dinv[row];
    int c = lane * 2;
    float r0 = fmaxf(acc.x * drow + b1[c], 0.f);        // a1[row][c]
    float r1 = fmaxf(acc.y * drow + b1[c + 1], 0.f);    // a1[row][c+1]

    // fused gemm2: W2 is [64,2] row-major; lane's float4 = W2[c][0],W2[c][1],W2[c+1][0],W2[c+1][1]
    float4 w2 = *(const float4*)&W2[c * 2];
    float p0 = r0 * w2.x + r1 * w2.z;
    float p1 = r0 * w2.y + r1 * w2.w;
    #pragma unroll
    for (int o = 16; o > 0; o >>= 1) {
        p0 += __shfl_xor_sync(0xffffffffu, p0, o);
        p1 += __shfl_xor_sync(0xffffffffu, p1, o);
    }
    if (lane == 0)
        *(float2*)&g_h2s[(size_t)row * OD] = make_float2(p0 * drow, p1 * drow);
}

// ---------------- gather2 (+ cnt re-zero for next replay) ----------------

__global__ void __launch_bounds__(256) k_gather2(const float* __restrict__ b2,
                                                 float* __restrict__ out, int n) {
    int lane = threadIdx.x & 31;
    int row = blockIdx.x * 8 + (threadIdx.x >> 5);
    if (row >= n) return;
    int start = g_rowstart[row];
    int end   = g_rowend[row];

    float2 acc = make_float2(0.f, 0.f);
    for (int j = start + lane; j < end; j += 32) {
        int s = g_csr[j];
        float2 v = *(const float2*)&g_h2s[(size_t)s * OD];
        acc.x += v.x; acc.y += v.y;
    }
    #pragma unroll
    for (int o = 16; o > 0; o >>= 1) {
        acc.x += __shfl_xor_sync(0xffffffffu, acc.x, o);
        acc.y += __shfl_xor_sync(0xffffffffu, acc.y, o);
    }
    if (lane == 0) {
        g_cnt[row] = 0;                      // dead after offsets; ready for next call
        float2 self = *(const float2*)&g_h2s[(size_t)row * OD];
        float d = g_dinv[row];
        *(float2*)&out[(size_t)row * OD] =
            make_float2((acc.x + self.x) * d + b2[0],
                        (acc.y + self.y) * d + b2[1]);
    }
}

// ---------------- launch (fork/join: gemm1 concurrent with hist/offsets/fill) ----------------

extern "C" void kernel_launch(void* const* d_in, const int* in_sizes, int n_in,
                              void* d_out, int out_size) {
    const float* x  = (const float*)d_in[0];
    const int*   ei = (const int*)d_in[1];       // int32 (JAX x64 disabled)
    const float* W1 = (const float*)d_in[2];
    const float* b1 = (const float*)d_in[3];
    const float* W2 = (const float*)d_in[4];
    const float* b2 = (const float*)d_in[5];
    float* out = (float*)d_out;

    int n = in_sizes[0] / IND;    // 100000
    int e = in_sizes[1] / 2;      // 3200000
    int nb256 = (n + 255) / 256;

    const int SMEM = (IND * HD + TILE_R * IND) * sizeof(float);   // 96 KB
    cudaFuncSetAttribute(k_gemm1, cudaFuncAttributeMaxDynamicSharedMemorySize, SMEM);

    // lazily-created side stream + events (created once, on the first/correctness
    // call; enqueued work is identical on every call)
    static cudaStream_t s2 = nullptr;
    static cudaEvent_t evFork = nullptr, evJoin = nullptr;
    if (!s2) {
        cudaStreamCreate(&s2);
        cudaEventCreateWithFlags(&evFork, cudaEventDisableTiming);
        cudaEventCreateWithFlags(&evJoin, cudaEventDisableTiming);
    }

    // fork: gemm1 on s2, independent of CSR chain
    cudaEventRecord(evFork, 0);
    cudaStreamWaitEvent(s2, evFork, 0);
    k_gemm1<<<GEMM1_BLOCKS, 256, SMEM, s2>>>(x, W1, n);
    cudaEventRecord(evJoin, s2);

    // CSR chain on default stream
    k_hist   <<<2048, 256>>>(ei, e);
    k_offsets<<<nb256, 256>>>(n);
    k_fill   <<<2048, 256>>>(ei, e);

    // join, then consumers
    cudaStreamWaitEvent(0, evJoin, 0);
    k_scale  <<<(n * (HD / 2) + 255) / 256, 256>>>(n);
    k_gather1f<<<(n + 7) / 8, 256>>>(b1, W2, n);
    k_gather2 <<<(n + 7) / 8, 256>>>(b2, out, n);
}